// round 6
// baseline (speedup 1.0000x reference)
#include <cuda_runtime.h>
#include <math.h>

#define HH 512
#define WW 512
#define BB 16
#define IMG (HH*WW)            // 262144 = 1<<18
#define TOT (BB*IMG)           // 4194304
#define NTILES 4096            // 16 x-tiles * 16 y-tiles * 16 images
#define MAXR 48
#define RIDS 160               // stamp/round id space: bases 0,49,98
#define NEG (-INFINITY)

// Scratch (static __device__ arrays: allocation-free)
__device__ float g_m  [TOT];
__device__ float g_m2 [TOT];
__device__ float g_rmx[TOT];
__device__ float g_m3 [TOT];
__device__ int   g_queue[2][NTILES];
__device__ int   g_qstamp[NTILES];
__device__ int   g_qtail[RIDS];
__device__ int   g_qhead[RIDS];
__device__ int   g_rflags[2];          // [0]: any Rmax==0, [1]: any Rmax==1
__device__ float g_cc[BB];
__device__ unsigned g_arrive  = 0;
__device__ unsigned g_release = 0;

// ---------------------------------------------------------------------------
// Software grid barrier (all blocks co-resident by construction).
// ---------------------------------------------------------------------------
__device__ __forceinline__ void gbar(unsigned nb, unsigned& target)
{
    __syncthreads();
    if (threadIdx.x == 0) {
        __threadfence();
        unsigned old = atomicInc(&g_arrive, nb - 1);
        if (old == nb - 1) {
            atomicAdd(&g_release, 1);
        } else {
            while (*((volatile unsigned*)&g_release) < target) __nanosleep(32);
        }
        __threadfence();
    }
    target++;
    __syncthreads();
}

// Edge-change bits for cell (row 4*ty+k, col tx) of a 32x32 tile.
// bit0 top,1 bottom,2 left,3 right,4 TL,5 TR,6 BL,7 BR  (bit8 = self/cap)
__device__ __forceinline__ unsigned edgebits(int ty, int k, int tx)
{
    unsigned e = 0;
    bool top = (ty == 0 && k == 0), bot = (ty == 7 && k == 3);
    if (top) e |= 1u;
    if (bot) e |= 2u;
    if (tx == 0) e |= 4u;
    if (tx == 31) e |= 8u;
    if (top && tx == 0)  e |= 16u;
    if (top && tx == 31) e |= 32u;
    if (bot && tx == 0)  e |= 64u;
    if (bot && tx == 31) e |= 128u;
    return e;
}

// ---------------------------------------------------------------------------
// Block-per-tile solver: per-iteration exact horizontal row fixpoint via warp
// clamp-function scans (composition (c2,d2)o(c1,d1) = (min(c2,max(d2,c1)),
// max(d2,d1)); applied to -inf gives min(C,D); max of L/R scans = exact 1D
// fixpoint), then 3x3 chaotic Gauss-Seidel sweep (diagonals + certification).
// Monotone max-lattice => all races benign; "no change in full 3x3 pass" is
// an exact tile-fixpoint test. On change, pushes affected neighbors (edge-
// filtered) into next round's deduped queue; pushes itself on cap-hit.
// ---------------------------------------------------------------------------
__device__ void process_tile(
    float* __restrict__ mk, const float* __restrict__ msk,
    int t, int stamp, int fillpar, float (*sm)[34], int* sEdge, int tid)
{
    const int img = t >> 8, local = t & 255;
    const int x0 = (local & 15) << 5, y0 = ((local >> 4) & 15) << 5;
    float* m        = mk  + (size_t)img * IMG;
    const float* ms = msk + (size_t)img * IMG;
    const int ty = tid >> 5, tx = tid & 31;          // ty 0..7, tx(lane) 0..31
    const int sy = tid >> 3, sxs = (tid & 7) << 2;   // staging: row, 4-col seg

    __syncthreads();                                  // protect prev visit's sm
    if (tid == 0) *sEdge = 0;

    // ---- stage interior 32x32 (float4, x0 is 32-aligned) ----
    {
        float4 v = __ldcg((const float4*)&m[(y0 + sy) * WW + x0 + sxs]);
        sm[sy + 1][sxs + 1] = v.x;
        sm[sy + 1][sxs + 2] = v.y;
        sm[sy + 1][sxs + 3] = v.z;
        sm[sy + 1][sxs + 4] = v.w;
    }
    // ---- halo (132 cells, -inf outside image) ----
    if (tid < 132) {
        int ly, lx, gy, gx;
        if (tid < 34)        { ly = 0;        lx = tid;       gy = y0 - 1;         gx = x0 + tid - 1;  }
        else if (tid < 68)   { ly = 33;       lx = tid - 34;  gy = y0 + 32;        gx = x0 + tid - 35; }
        else if (tid < 100)  { ly = tid - 67; lx = 0;         gy = y0 + tid - 68;  gx = x0 - 1;        }
        else                 { ly = tid - 99; lx = 33;        gy = y0 + tid - 100; gx = x0 + 32;       }
        float v = NEG;
        if ((unsigned)gx < WW && (unsigned)gy < HH) v = __ldcg(&m[gy * WW + gx]);
        sm[ly][lx] = v;
    }

    float mval[4], cur[4];
#pragma unroll
    for (int k = 0; k < 4; k++)
        mval[k] = __ldg(&ms[(y0 + 4 * ty + k) * WW + x0 + tx]);
    __syncthreads();
#pragma unroll
    for (int k = 0; k < 4; k++)
        cur[k] = sm[4 * ty + k + 1][tx + 1];

    bool any = false, lastc = false;
    unsigned em = 0;
    for (int it = 0; it < 32; ++it) {
        bool ch = false;
        // ---- B: exact horizontal row fixpoint (register clamp-scans) ----
#pragma unroll
        for (int k = 0; k < 4; k++) {
            float c = mval[k], d = cur[k];
            float c2 = c, d2 = d;
#pragma unroll
            for (int s = 1; s < 32; s <<= 1) {
                float c1 = __shfl_up_sync(0xffffffffu, c, s);
                float d1 = __shfl_up_sync(0xffffffffu, d, s);
                if (tx >= s) { c = fminf(c, fmaxf(d, c1)); d = fmaxf(d, d1); }
            }
#pragma unroll
            for (int s = 1; s < 32; s <<= 1) {
                float c1 = __shfl_down_sync(0xffffffffu, c2, s);
                float d1 = __shfl_down_sync(0xffffffffu, d2, s);
                if (tx + s < 32) { c2 = fminf(c2, fmaxf(d2, c1)); d2 = fmaxf(d2, d1); }
            }
            float nv = fmaxf(fminf(c, d), fminf(c2, d2));
            if (nv > cur[k]) {
                cur[k] = nv; sm[4 * ty + k + 1][tx + 1] = nv;
                ch = true; em |= edgebits(ty, k, tx);
            }
        }
        __syncthreads();
        // ---- A: 3x3 GS down sweep (vertical regs; horiz/diag via live smem)
#pragma unroll
        for (int k = 0; k < 4; k++) {
            const int r = 4 * ty + k;                 // smem row of up-nbrs
            float up_c = (k > 0) ? cur[k - 1] : sm[r][tx + 1];
            float dn_c = (k < 3) ? cur[k + 1] : sm[r + 2][tx + 1];
            float c = fmaxf(fmaxf(sm[r][tx], up_c), sm[r][tx + 2]);
            c = fmaxf(c, fmaxf(sm[r + 1][tx], sm[r + 1][tx + 2]));
            c = fmaxf(c, fmaxf(fmaxf(sm[r + 2][tx], dn_c), sm[r + 2][tx + 2]));
            float nv = fminf(mval[k], fmaxf(cur[k], c));
            if (nv > cur[k]) {
                cur[k] = nv; sm[r + 1][tx + 1] = nv;
                ch = true; em |= edgebits(ty, k, tx);
            }
        }
        // up sweep (register-only vertical back-propagation)
#pragma unroll
        for (int k = 2; k >= 0; k--) {
            float nv = fminf(mval[k], fmaxf(cur[k], cur[k + 1]));
            if (nv > cur[k]) {
                cur[k] = nv; sm[4 * ty + k + 1][tx + 1] = nv;
                ch = true; em |= edgebits(ty, k, tx);
            }
        }
        any |= ch;
        lastc = __syncthreads_or(ch);
        if (!lastc) break;
    }

    if (em) atomicOr(sEdge, (int)em);
    if (tid == 0 && lastc) atomicOr(sEdge, 256);      // cap-hit: re-wake self
    bool blkany = __syncthreads_or(any);
    if (blkany) {
        float4 v;
        v.x = sm[sy + 1][sxs + 1];
        v.y = sm[sy + 1][sxs + 2];
        v.z = sm[sy + 1][sxs + 3];
        v.w = sm[sy + 1][sxs + 4];
        __stcg((float4*)&m[(y0 + sy) * WW + x0 + sxs], v);
    }
    // ---- push woken neighbors into next round's queue (deduped) ----
    if (tid < 9) {
        int e = *sEdge;
        if (e & (1 << tid)) {
            const int tyy = (t >> 4) & 15, txx = t & 15;
            int nt = -1;
            switch (tid) {
                case 0: if (tyy > 0)               nt = t - 16; break;
                case 1: if (tyy < 15)              nt = t + 16; break;
                case 2: if (txx > 0)               nt = t - 1;  break;
                case 3: if (txx < 15)              nt = t + 1;  break;
                case 4: if (tyy > 0  && txx > 0)   nt = t - 17; break;
                case 5: if (tyy > 0  && txx < 15)  nt = t - 15; break;
                case 6: if (tyy < 15 && txx > 0)   nt = t + 15; break;
                case 7: if (tyy < 15 && txx < 15)  nt = t + 17; break;
                case 8:                            nt = t;      break;
            }
            if (nt >= 0 && atomicExch(&g_qstamp[nt], stamp) != stamp) {
                int s = atomicAdd(&g_qtail[stamp], 1);
                __stcg(&g_queue[fillpar][s], nt);
            }
        }
    }
}

// ---------------------------------------------------------------------------
// Reconstruction: round 0 = static pass over all tiles; later rounds pop only
// woken tiles from the deduped queue. Exact termination: next queue empty.
// ---------------------------------------------------------------------------
__device__ __forceinline__ void recon(
    float* mk, const float* msk, int base,
    unsigned nb, unsigned& target, float (*sm)[34], int* sEdge, int* sItem,
    int tid, int bid)
{
    for (int r = 0; r < MAXR; ++r) {
        const int stamp = base + r + 1;               // globally unique
        const int fillpar = (r + 1) & 1;
        if (r == 0) {
            for (int t = bid; t < NTILES; t += (int)nb)
                process_tile(mk, msk, t, stamp, fillpar, sm, sEdge, tid);
        } else {
            const int cnt = __ldcg(&g_qtail[base + r]);
            const int par = r & 1;
            for (;;) {
                if (tid == 0) {
                    int i = atomicAdd(&g_qhead[base + r], 1);
                    *sItem = (i < cnt) ? __ldcg(&g_queue[par][i]) : -1;
                }
                __syncthreads();
                int t = *sItem;
                if (t < 0) break;                      // uniform
                process_tile(mk, msk, t, stamp, fillpar, sm, sEdge, tid);
            }
        }
        gbar(nb, target);
        if (__ldcg(&g_qtail[base + r + 1]) == 0) break;  // uniform, exact
    }
}

// ---------------------------------------------------------------------------
// The whole pipeline in one persistent kernel.
// ---------------------------------------------------------------------------
__global__ void __launch_bounds__(256, 6) persistent_kernel(
    const float* __restrict__ x, const float* __restrict__ h,
    const float* __restrict__ u, float* __restrict__ out, int nbi)
{
    __shared__ float sm[34][34];
    __shared__ float red[8];
    __shared__ int sEdge, sItem;
    const unsigned nb = (unsigned)nbi;
    const int tid = threadIdx.x;
    const int bid = blockIdx.x;
    const int gid = bid * 256 + tid;
    const int nthr = nbi * 256;
    unsigned target = *((volatile unsigned*)&g_release) + 1;

    // ---- P0: g_m = x - h ; reset queue state / flags / counters ----------
    {
        const float4* x4 = (const float4*)x;
        float4* m4 = (float4*)g_m;
        for (int i4 = gid; i4 < TOT / 4; i4 += nthr) {
            float4 v = __ldg(&x4[i4]);
            float hh = __ldg(&h[i4 >> 16]);
            v.x -= hh; v.y -= hh; v.z -= hh; v.w -= hh;
            __stcg(&m4[i4], v);
        }
        for (int i = gid; i < NTILES; i += nthr) __stcg(&g_qstamp[i], 0);
        if (gid < RIDS) { __stcg(&g_qtail[gid], 0); __stcg(&g_qhead[gid], 0); }
        if (bid == 0) {
            if (tid < 2)  __stcg(&g_rflags[tid], 0);
            if (tid < BB) __stcg(&g_cc[tid], 0.0f);
        }
    }
    gbar(nb, target);

    // ---- Rec1: xh = rec(x - h, x) ----------------------------------------
    recon(g_m, x, 0, nb, target, sm, &sEdge, &sItem, tid, bid);

    // ---- P1: out[16..] = xh ; g_m2 = xh - eps ----------------------------
    {
        const float4* m4 = (const float4*)g_m;
        float4* m24 = (float4*)g_m2;
        float4* o4 = (float4*)(out + 16);
        for (int i4 = gid; i4 < TOT / 4; i4 += nthr) {
            float4 v = __ldcg(&m4[i4]);
            o4[i4] = v;
            v.x -= 1e-5f; v.y -= 1e-5f; v.z -= 1e-5f; v.w -= 1e-5f;
            __stcg(&m24[i4], v);
        }
    }
    gbar(nb, target);

    // ---- Rec2: rec(xh - eps, xh) -----------------------------------------
    recon(g_m2, g_m, 49, nb, target, sm, &sEdge, &sItem, tid, bid);

    // ---- P2: Rmax = (xh > rec2); M = min(u, Rmax); global min/max flags --
    {
        const float4* m4  = (const float4*)g_m;
        const float4* m24 = (const float4*)g_m2;
        const float4* u4  = (const float4*)u;
        float4* r4 = (float4*)g_rmx;
        float4* m34 = (float4*)g_m3;
        bool a0 = false, a1 = false;
        for (int i4 = gid; i4 < TOT / 4; i4 += nthr) {
            float4 a = __ldcg(&m4[i4]);
            float4 b = __ldcg(&m24[i4]);
            float4 uu = __ldg(&u4[i4]);
            float4 r, m3;
            r.x = (a.x > b.x) ? 1.0f : 0.0f;
            r.y = (a.y > b.y) ? 1.0f : 0.0f;
            r.z = (a.z > b.z) ? 1.0f : 0.0f;
            r.w = (a.w > b.w) ? 1.0f : 0.0f;
            if (r.x == 0.f || r.y == 0.f || r.z == 0.f || r.w == 0.f) a0 = true;
            if (r.x == 1.f || r.y == 1.f || r.z == 1.f || r.w == 1.f) a1 = true;
            m3.x = fminf(uu.x, r.x); m3.y = fminf(uu.y, r.y);
            m3.z = fminf(uu.z, r.z); m3.w = fminf(uu.w, r.w);
            __stcg(&r4[i4], r);
            __stcg(&m34[i4], m3);
        }
        bool b0 = __syncthreads_or(a0);
        bool b1 = __syncthreads_or(a1);
        if (tid == 0) {
            if (b0) atomicExch(&g_rflags[0], 1);
            if (b1) atomicExch(&g_rflags[1], 1);
        }
    }
    gbar(nb, target);

    // ---- Rec3: R = rec(M, Rmax) ------------------------------------------
    recon(g_m3, g_rmx, 98, nb, target, sm, &sEdge, &sItem, tid, bid);

    // ---- P3: CC[img] = sum(u == R) ---------------------------------------
    {
        const int ty = tid >> 5, tx = tid & 31;
        for (int t = bid; t < NTILES; t += nbi) {
            int img = t >> 8, local = t & 255;
            int x0 = (local & 15) << 5, y0 = ((local >> 4) & 15) << 5;
            const float* uu = u + (size_t)img * IMG;
            const float* m3 = g_m3 + (size_t)img * IMG;
            float s = 0.0f;
#pragma unroll
            for (int k = 0; k < 4; k++) {
                int idx = (y0 + ty + 8 * k) * WW + x0 + tx;
                s += (__ldg(&uu[idx]) == __ldcg(&m3[idx])) ? 1.0f : 0.0f;
            }
#pragma unroll
            for (int off = 16; off; off >>= 1)
                s += __shfl_down_sync(0xffffffffu, s, off);
            if ((tid & 31) == 0) red[tid >> 5] = s;
            __syncthreads();
            if (tid == 0) {
                float tot = 0.0f;
#pragma unroll
                for (int w = 0; w < 8; w++) tot += red[w];
                atomicAdd(&g_cc[img], tot);
            }
            __syncthreads();
        }
    }
    gbar(nb, target);

    // ---- P4: CC_ ---------------------------------------------------------
    if (bid == 0 && tid < BB) {
        float maxR = __ldcg(&g_rflags[1]) ? 1.0f : 0.0f;
        float minR = __ldcg(&g_rflags[0]) ? 0.0f : 1.0f;
        float diff = maxR - minR;
        float cc = *(volatile float*)&g_cc[tid];
        out[tid] = fminf(cc, 100.0f * diff * cc);
    }
}

// ---------------------------------------------------------------------------
extern "C" void kernel_launch(void* const* d_in, const int* in_sizes, int n_in,
                              void* d_out, int out_size)
{
    // Identify inputs by size (x and u are 4194304, h is 16; x precedes u)
    const float *x = nullptr, *h = nullptr, *u = nullptr;
    for (int i = 0; i < n_in; i++) {
        if (in_sizes[i] == BB) h = (const float*)d_in[i];
        else if (!x)           x = (const float*)d_in[i];
        else                   u = (const float*)d_in[i];
    }
    float* out = (float*)d_out;

    int dev = 0, sms = 0, occ = 0;
    cudaGetDevice(&dev);
    cudaDeviceGetAttribute(&sms, cudaDevAttrMultiProcessorCount, dev);
    cudaOccupancyMaxActiveBlocksPerMultiprocessor(&occ, persistent_kernel, 256, 0);
    int nb = sms * occ;
    if (nb <= 0) nb = 256;       // conservative fallback, guaranteed resident
    if (nb > 2048) nb = 2048;

    persistent_kernel<<<nb, 256>>>(x, h, u, out, nb);
}

// round 7
// speedup vs baseline: 1.5981x; 1.5981x over previous
#include <cuda_runtime.h>
#include <math.h>

#define HH 512
#define WW 512
#define BB 16
#define IMG (HH*WW)            // 262144 = 1<<18
#define TOT (BB*IMG)           // 4194304
#define NTILES 4096            // 16 x-tiles * 16 y-tiles * 16 images
#define MAXR1 28
#define MAXR2 28
#define MAXR3 16
#define NFLAGS (MAXR1+MAXR2+MAXR3)
#define NEG (-INFINITY)

// Scratch (static __device__ arrays: allocation-free)
__device__ float g_m  [TOT];
__device__ float g_m2 [TOT];
__device__ float g_rmx[TOT];
__device__ float g_m3 [TOT];
__device__ unsigned char g_dirty[2][NTILES];
__device__ int   g_chflag[NFLAGS];
__device__ int   g_rflags[2];          // [0]: any Rmax==0, [1]: any Rmax==1
__device__ float g_cc[BB];
__device__ unsigned g_arrive  = 0;
__device__ unsigned g_release = 0;

// ---------------------------------------------------------------------------
// Software grid barrier (all blocks co-resident by construction).
// ---------------------------------------------------------------------------
__device__ __forceinline__ void gbar(unsigned nb, unsigned& target)
{
    __syncthreads();
    if (threadIdx.x == 0) {
        __threadfence();
        unsigned old = atomicInc(&g_arrive, nb - 1);
        if (old == nb - 1) {
            atomicAdd(&g_release, 1);
        } else {
            while (*((volatile unsigned*)&g_release) < target) __nanosleep(32);
        }
        __threadfence();
    }
    target++;
    __syncthreads();
}

// ---------------------------------------------------------------------------
// Exact 1-D horizontal row fixpoint via warp clamp-function scans.
// g_i(x)=min(m_i,max(v_i,x)); compositions stay clamps:
// (c2,d2)o(c1,d1) = (min(c2,max(d2,c1)), max(d2,d1)). Row fixpoint =
// max(L->R scan value, R->L scan value), each = min(C,D) of the inclusive
// composition applied to -inf. Updates cur[] and smem; returns "changed".
// ---------------------------------------------------------------------------
__device__ __forceinline__ bool hscan_rows(
    float cur[4], const float mval[4], float (*sm)[34], int ty, int tx)
{
    bool ch = false;
#pragma unroll
    for (int k = 0; k < 4; k++) {
        float c = mval[k], d = cur[k];
        float c2 = c, d2 = d;
#pragma unroll
        for (int s = 1; s < 32; s <<= 1) {
            float c1 = __shfl_up_sync(0xffffffffu, c, s);
            float d1 = __shfl_up_sync(0xffffffffu, d, s);
            if (tx >= s) { c = fminf(c, fmaxf(d, c1)); d = fmaxf(d, d1); }
        }
#pragma unroll
        for (int s = 1; s < 32; s <<= 1) {
            float c1 = __shfl_down_sync(0xffffffffu, c2, s);
            float d1 = __shfl_down_sync(0xffffffffu, d2, s);
            if (tx + s < 32) { c2 = fminf(c2, fmaxf(d2, c1)); d2 = fmaxf(d2, d1); }
        }
        float nv = fmaxf(fminf(c, d), fminf(c2, d2));
        if (nv > cur[k]) {
            cur[k] = nv;
            sm[4 * ty + k + 1][tx + 1] = nv;
            ch = true;
        }
    }
    return ch;
}

// ---------------------------------------------------------------------------
// Block-per-tile chaotic Gauss-Seidel relaxation (R4) + entry/periodic exact
// horizontal scans. Thread (tx,ty) owns 4 CONTIGUOUS rows of column tx.
// In-place smem updates; races benign (monotone max-lattice); "no change in
// a full 3x3 pass" is an exact tile-fixpoint certificate.
// ---------------------------------------------------------------------------
__device__ __forceinline__ bool process_tile(
    float* __restrict__ mk, const float* __restrict__ msk,
    int img, int x0, int y0, float (*sm)[34], int tid)
{
    float* m        = mk  + (size_t)img * IMG;
    const float* ms = msk + (size_t)img * IMG;
    const int ty = tid >> 5, tx = tid & 31;          // ty 0..7, tx 0..31
    const int sy = tid >> 3, sxs = (tid & 7) << 2;   // staging: row, 4-col seg

    // ---- stage interior 32x32 (float4, 32-aligned) ----
    {
        float4 v = __ldcg((const float4*)&m[(y0 + sy) * WW + x0 + sxs]);
        sm[sy + 1][sxs + 1] = v.x;
        sm[sy + 1][sxs + 2] = v.y;
        sm[sy + 1][sxs + 3] = v.z;
        sm[sy + 1][sxs + 4] = v.w;
    }
    // ---- halo (132 cells, -inf outside image) ----
    if (tid < 132) {
        int ly, lx, gy, gx;
        if (tid < 34)        { ly = 0;        lx = tid;       gy = y0 - 1;         gx = x0 + tid - 1;  }
        else if (tid < 68)   { ly = 33;       lx = tid - 34;  gy = y0 + 32;        gx = x0 + tid - 35; }
        else if (tid < 100)  { ly = tid - 67; lx = 0;         gy = y0 + tid - 68;  gx = x0 - 1;        }
        else                 { ly = tid - 99; lx = 33;        gy = y0 + tid - 100; gx = x0 + 32;       }
        float v = NEG;
        if ((unsigned)gx < WW && (unsigned)gy < HH) v = __ldcg(&m[gy * WW + gx]);
        sm[ly][lx] = v;
    }

    float mval[4], cur[4];
#pragma unroll
    for (int k = 0; k < 4; k++)
        mval[k] = __ldg(&ms[(y0 + 4 * ty + k) * WW + x0 + tx]);
    __syncthreads();
#pragma unroll
    for (int k = 0; k < 4; k++)
        cur[k] = sm[4 * ty + k + 1][tx + 1];

    // ---- entry: exact horizontal row fixpoint ----
    bool any = hscan_rows(cur, mval, sm, ty, tx);
    __syncthreads();

    for (int it = 0; it < 48; ++it) {
        bool ch = false;
        // periodic horizontal rescan (handles staircase paths)
        if ((it & 3) == 3) {
            ch = hscan_rows(cur, mval, sm, ty, tx);
            __syncthreads();
        }
        // down sweep (GS vertical via registers; horizontal/diag via live smem)
#pragma unroll
        for (int k = 0; k < 4; k++) {
            const int r = 4 * ty + k;                     // smem row of up-nbrs
            float up_c = (k > 0) ? cur[k - 1] : sm[r][tx + 1];
            float dn_c = (k < 3) ? cur[k + 1] : sm[r + 2][tx + 1];
            float c = fmaxf(fmaxf(sm[r][tx], up_c), sm[r][tx + 2]);
            c = fmaxf(c, fmaxf(sm[r + 1][tx], sm[r + 1][tx + 2]));
            c = fmaxf(c, fmaxf(fmaxf(sm[r + 2][tx], dn_c), sm[r + 2][tx + 2]));
            float nv = fminf(mval[k], fmaxf(cur[k], c));
            if (nv > cur[k]) { cur[k] = nv; sm[r + 1][tx + 1] = nv; ch = true; }
        }
        // up sweep (register-only vertical back-propagation)
#pragma unroll
        for (int k = 2; k >= 0; k--) {
            float nv = fminf(mval[k], fmaxf(cur[k], cur[k + 1]));
            if (nv > cur[k]) { cur[k] = nv; sm[4 * ty + k + 1][tx + 1] = nv; ch = true; }
        }
        any |= ch;
        if (!__syncthreads_or(ch)) break;
    }

    bool blkany = __syncthreads_or(any);
    if (blkany) {
        float4 v;
        v.x = sm[sy + 1][sxs + 1];
        v.y = sm[sy + 1][sxs + 2];
        v.z = sm[sy + 1][sxs + 3];
        v.w = sm[sy + 1][sxs + 4];
        __stcg((float4*)&m[(y0 + sy) * WW + x0 + sxs], v);
    }
    return blkany;
}

// ---------------------------------------------------------------------------
// Reconstruction: rounds of tile relaxation with dirty-skip + exact early exit.
// ---------------------------------------------------------------------------
__device__ __forceinline__ void recon(
    float* mk, const float* msk, int maxr, int flagbase,
    unsigned nb, unsigned& target, float (*sm)[34], int tid, int bid)
{
    for (int r = 0; r < maxr; ++r) {
        const int par = r & 1;
        for (int t = bid; t < NTILES; t += (int)nb) {
            bool need = true;
            if (r > 0) {
                bool mine = false;
                if (tid < 9) {
                    int dy = tid / 3 - 1, dx = tid % 3 - 1;
                    int tyy = (t >> 4) & 15, txx = t & 15;
                    int ny = tyy + dy, nx = txx + dx;
                    if ((unsigned)ny < 16u && (unsigned)nx < 16u)
                        mine = (*(volatile unsigned char*)&g_dirty[par ^ 1][t + dy * 16 + dx]) != 0;
                }
                need = __syncthreads_or(mine);
            }
            bool ch = false;
            if (need) {
                int img = t >> 8, local = t & 255;
                ch = process_tile(mk, msk, img, (local & 15) << 5, ((local >> 4) & 15) << 5, sm, tid);
            }
            if (tid == 0) {
                *(volatile unsigned char*)&g_dirty[par][t] = ch ? 1 : 0;
                if (ch) *(volatile int*)&g_chflag[flagbase + r] = 1;
            }
            __syncthreads();
        }
        gbar(nb, target);
        if (*(volatile int*)&g_chflag[flagbase + r] == 0) break;  // uniform
    }
}

// ---------------------------------------------------------------------------
// The whole pipeline in one persistent kernel.
// ---------------------------------------------------------------------------
__global__ void __launch_bounds__(256, 6) persistent_kernel(
    const float* __restrict__ x, const float* __restrict__ h,
    const float* __restrict__ u, float* __restrict__ out, int nbi)
{
    __shared__ float sm[34][34];
    __shared__ float red[8];
    const unsigned nb = (unsigned)nbi;
    const int tid = threadIdx.x;
    const int bid = blockIdx.x;
    const int gid = bid * 256 + tid;
    const int nthr = nbi * 256;
    unsigned target = *((volatile unsigned*)&g_release) + 1;

    // ---- P0: g_m = x - h ; reset flags/counters --------------------------
    {
        const float4* x4 = (const float4*)x;
        float4* m4 = (float4*)g_m;
        for (int i4 = gid; i4 < TOT / 4; i4 += nthr) {
            float4 v = __ldg(&x4[i4]);
            float hh = __ldg(&h[i4 >> 16]);
            v.x -= hh; v.y -= hh; v.z -= hh; v.w -= hh;
            __stcg(&m4[i4], v);
        }
        if (bid == 0) {
            if (tid < NFLAGS) __stcg(&g_chflag[tid], 0);
            if (tid < 2)      __stcg(&g_rflags[tid], 0);
            if (tid < BB)     __stcg(&g_cc[tid], 0.0f);
        }
    }
    gbar(nb, target);

    // ---- Rec1: xh = rec(x - h, x) ----------------------------------------
    recon(g_m, x, MAXR1, 0, nb, target, sm, tid, bid);

    // ---- P1: out[16..] = xh ; g_m2 = xh - eps ----------------------------
    {
        const float4* m4 = (const float4*)g_m;
        float4* m24 = (float4*)g_m2;
        float4* o4 = (float4*)(out + 16);
        for (int i4 = gid; i4 < TOT / 4; i4 += nthr) {
            float4 v = __ldcg(&m4[i4]);
            o4[i4] = v;
            v.x -= 1e-5f; v.y -= 1e-5f; v.z -= 1e-5f; v.w -= 1e-5f;
            __stcg(&m24[i4], v);
        }
    }
    gbar(nb, target);

    // ---- Rec2: rec(xh - eps, xh) -----------------------------------------
    recon(g_m2, g_m, MAXR2, MAXR1, nb, target, sm, tid, bid);

    // ---- P2: Rmax = (xh > rec2); M = min(u, Rmax); global min/max flags --
    {
        const float4* m4  = (const float4*)g_m;
        const float4* m24 = (const float4*)g_m2;
        const float4* u4  = (const float4*)u;
        float4* r4 = (float4*)g_rmx;
        float4* m34 = (float4*)g_m3;
        bool a0 = false, a1 = false;
        for (int i4 = gid; i4 < TOT / 4; i4 += nthr) {
            float4 a = __ldcg(&m4[i4]);
            float4 b = __ldcg(&m24[i4]);
            float4 uu = __ldg(&u4[i4]);
            float4 r, m3;
            r.x = (a.x > b.x) ? 1.0f : 0.0f;
            r.y = (a.y > b.y) ? 1.0f : 0.0f;
            r.z = (a.z > b.z) ? 1.0f : 0.0f;
            r.w = (a.w > b.w) ? 1.0f : 0.0f;
            if (r.x == 0.f || r.y == 0.f || r.z == 0.f || r.w == 0.f) a0 = true;
            if (r.x == 1.f || r.y == 1.f || r.z == 1.f || r.w == 1.f) a1 = true;
            m3.x = fminf(uu.x, r.x); m3.y = fminf(uu.y, r.y);
            m3.z = fminf(uu.z, r.z); m3.w = fminf(uu.w, r.w);
            __stcg(&r4[i4], r);
            __stcg(&m34[i4], m3);
        }
        bool b0 = __syncthreads_or(a0);
        bool b1 = __syncthreads_or(a1);
        if (tid == 0) {
            if (b0) *(volatile int*)&g_rflags[0] = 1;
            if (b1) *(volatile int*)&g_rflags[1] = 1;
        }
    }
    gbar(nb, target);

    // ---- Rec3: R = rec(M, Rmax) ------------------------------------------
    recon(g_m3, g_rmx, MAXR3, MAXR1 + MAXR2, nb, target, sm, tid, bid);

    // ---- P3: CC[img] = sum(u == R) ---------------------------------------
    {
        const int ty = tid >> 5, tx = tid & 31;
        for (int t = bid; t < NTILES; t += nbi) {
            int img = t >> 8, local = t & 255;
            int x0 = (local & 15) << 5, y0 = ((local >> 4) & 15) << 5;
            const float* uu = u + (size_t)img * IMG;
            const float* m3 = g_m3 + (size_t)img * IMG;
            float s = 0.0f;
#pragma unroll
            for (int k = 0; k < 4; k++) {
                int idx = (y0 + ty + 8 * k) * WW + x0 + tx;
                s += (__ldg(&uu[idx]) == __ldcg(&m3[idx])) ? 1.0f : 0.0f;
            }
#pragma unroll
            for (int off = 16; off; off >>= 1)
                s += __shfl_down_sync(0xffffffffu, s, off);
            if ((tid & 31) == 0) red[tid >> 5] = s;
            __syncthreads();
            if (tid == 0) {
                float tot = 0.0f;
#pragma unroll
                for (int w = 0; w < 8; w++) tot += red[w];
                atomicAdd(&g_cc[img], tot);
            }
            __syncthreads();
        }
    }
    gbar(nb, target);

    // ---- P4: CC_ ---------------------------------------------------------
    if (bid == 0 && tid < BB) {
        float maxR = (*(volatile int*)&g_rflags[1]) ? 1.0f : 0.0f;
        float minR = (*(volatile int*)&g_rflags[0]) ? 0.0f : 1.0f;
        float diff = maxR - minR;
        float cc = *(volatile float*)&g_cc[tid];
        out[tid] = fminf(cc, 100.0f * diff * cc);
    }
}

// ---------------------------------------------------------------------------
extern "C" void kernel_launch(void* const* d_in, const int* in_sizes, int n_in,
                              void* d_out, int out_size)
{
    // Identify inputs by size (x and u are 4194304, h is 16; x precedes u)
    const float *x = nullptr, *h = nullptr, *u = nullptr;
    for (int i = 0; i < n_in; i++) {
        if (in_sizes[i] == BB) h = (const float*)d_in[i];
        else if (!x)           x = (const float*)d_in[i];
        else                   u = (const float*)d_in[i];
    }
    float* out = (float*)d_out;

    int dev = 0, sms = 0, occ = 0;
    cudaGetDevice(&dev);
    cudaDeviceGetAttribute(&sms, cudaDevAttrMultiProcessorCount, dev);
    cudaOccupancyMaxActiveBlocksPerMultiprocessor(&occ, persistent_kernel, 256, 0);
    int nb = sms * occ;
    if (nb <= 0) nb = 256;       // conservative fallback, guaranteed resident
    if (nb > 2048) nb = 2048;

    persistent_kernel<<<nb, 256>>>(x, h, u, out, nb);
}

// round 8
// speedup vs baseline: 2.6000x; 1.6269x over previous
#include <cuda_runtime.h>
#include <math.h>

#define HH 512
#define WW 512
#define BB 16
#define IMG (HH*WW)            // 262144 = 1<<18
#define TOT (BB*IMG)           // 4194304
#define NTILES 4096            // 16 x-tiles * 16 y-tiles * 16 images
#define MAXR1 28
#define MAXR2 28
#define MAXR3 16
#define NFLAGS (MAXR1+MAXR2+MAXR3)
#define NEG (-INFINITY)

// Scratch (static __device__ arrays: allocation-free)
__device__ float g_m  [TOT];   // rec1 marker -> xh
__device__ float g_m2 [TOT];   // rec2 marker -> rec2
__device__ float g_rmx[TOT];   // Rmax (written during rec3 round 0)
__device__ float g_m3 [TOT];   // rec3 marker -> R
__device__ unsigned char g_dirty[2][NTILES];
__device__ int   g_chflag[NFLAGS];
__device__ int   g_rflags[2];          // [0]: any Rmax==0, [1]: any Rmax==1
__device__ float g_cc[BB];
__device__ unsigned g_arrive  = 0;
__device__ unsigned g_release = 0;

// ---------------------------------------------------------------------------
// Software grid barrier (all blocks co-resident by construction).
// ---------------------------------------------------------------------------
__device__ __forceinline__ void gbar(unsigned nb, unsigned& target)
{
    __syncthreads();
    if (threadIdx.x == 0) {
        __threadfence();
        unsigned old = atomicInc(&g_arrive, nb - 1);
        if (old == nb - 1) {
            atomicAdd(&g_release, 1);
        } else {
            while (*((volatile unsigned*)&g_release) < target) __nanosleep(32);
        }
        __threadfence();
    }
    target++;
    __syncthreads();
}

// ---------------------------------------------------------------------------
// Block-per-tile chaotic Gauss-Seidel relaxation (R4 solver, unchanged) with
// MODE-specialized round-0 staging that fuses the pointwise phases:
//   MODE 0: generic (rounds >=1): marker from mk (ldcg), mask from msk (ldg)
//   MODE 1: rec1 r0: marker = x - h computed on the fly (mask = x)
//   MODE 2: rec2 r0: mask = g_m; marker = mask - eps; writes xh tile to out
//   MODE 3: rec3 r0: mask = Rmax = (g_m > g_m2) (written to g_rmx); marker
//           = min(u, Rmax); folds global Rmax min/max flags
// Round-0 halo = initial marker (underestimate) — safe: monotone lattice +
// dirty-wake re-processing. Round-0 writeback unconditional (arrays start
// uninitialized). Races benign; "no change in a full 3x3 pass" is exact.
// ---------------------------------------------------------------------------
template<int MODE>
__device__ __forceinline__ bool process_tile(
    float* __restrict__ mk, const float* __restrict__ msk,
    const float* __restrict__ xg, const float* __restrict__ hg,
    const float* __restrict__ ug, float* __restrict__ outg,
    int img, int x0, int y0,
    float (*sm)[34], float (*smask)[32], int tid)
{
    const size_t base = (size_t)img * IMG;
    float* m = mk + base;
    const int ty = tid >> 5, tx = tid & 31;          // ty 0..7, tx 0..31
    const int sy = tid >> 3, sxs = (tid & 7) << 2;   // staging: row, 4-col seg
    const int irow = (y0 + sy) * WW + x0 + sxs;

    float hh = 0.0f;
    if (MODE == 1) hh = __ldg(&hg[img]);
    bool f0 = false, f1 = false;

    // ---- stage interior 32x32 (marker -> sm, mask -> smask) ----
    if (MODE == 0) {
        float4 v = __ldcg((const float4*)&m[irow]);
        sm[sy+1][sxs+1]=v.x; sm[sy+1][sxs+2]=v.y; sm[sy+1][sxs+3]=v.z; sm[sy+1][sxs+4]=v.w;
        float4 q = __ldg((const float4*)&msk[base + irow]);
        smask[sy][sxs]=q.x; smask[sy][sxs+1]=q.y; smask[sy][sxs+2]=q.z; smask[sy][sxs+3]=q.w;
    } else if (MODE == 1) {
        float4 q = __ldg((const float4*)&xg[base + irow]);
        smask[sy][sxs]=q.x; smask[sy][sxs+1]=q.y; smask[sy][sxs+2]=q.z; smask[sy][sxs+3]=q.w;
        sm[sy+1][sxs+1]=q.x-hh; sm[sy+1][sxs+2]=q.y-hh; sm[sy+1][sxs+3]=q.z-hh; sm[sy+1][sxs+4]=q.w-hh;
    } else if (MODE == 2) {
        float4 q = __ldg((const float4*)&msk[base + irow]);    // msk = g_m = xh
        *(float4*)&outg[16 + base + irow] = q;                 // emit xh output
        smask[sy][sxs]=q.x; smask[sy][sxs+1]=q.y; smask[sy][sxs+2]=q.z; smask[sy][sxs+3]=q.w;
        sm[sy+1][sxs+1]=q.x-1e-5f; sm[sy+1][sxs+2]=q.y-1e-5f; sm[sy+1][sxs+3]=q.z-1e-5f; sm[sy+1][sxs+4]=q.w-1e-5f;
    } else {
        float4 a  = __ldg((const float4*)&g_m [base + irow]);
        float4 b  = __ldg((const float4*)&g_m2[base + irow]);
        float4 uu = __ldg((const float4*)&ug  [base + irow]);
        float4 r;
        r.x = (a.x > b.x) ? 1.0f : 0.0f;
        r.y = (a.y > b.y) ? 1.0f : 0.0f;
        r.z = (a.z > b.z) ? 1.0f : 0.0f;
        r.w = (a.w > b.w) ? 1.0f : 0.0f;
        f0 = (r.x==0.f)||(r.y==0.f)||(r.z==0.f)||(r.w==0.f);
        f1 = (r.x==1.f)||(r.y==1.f)||(r.z==1.f)||(r.w==1.f);
        __stcg((float4*)&g_rmx[base + irow], r);               // persist mask
        smask[sy][sxs]=r.x; smask[sy][sxs+1]=r.y; smask[sy][sxs+2]=r.z; smask[sy][sxs+3]=r.w;
        sm[sy+1][sxs+1]=fminf(uu.x,r.x); sm[sy+1][sxs+2]=fminf(uu.y,r.y);
        sm[sy+1][sxs+3]=fminf(uu.z,r.z); sm[sy+1][sxs+4]=fminf(uu.w,r.w);
    }

    // ---- halo (132 cells, -inf outside image) ----
    if (tid < 132) {
        int ly, lx, gy, gx;
        if (tid < 34)        { ly = 0;        lx = tid;       gy = y0 - 1;         gx = x0 + tid - 1;  }
        else if (tid < 68)   { ly = 33;       lx = tid - 34;  gy = y0 + 32;        gx = x0 + tid - 35; }
        else if (tid < 100)  { ly = tid - 67; lx = 0;         gy = y0 + tid - 68;  gx = x0 - 1;        }
        else                 { ly = tid - 99; lx = 33;        gy = y0 + tid - 100; gx = x0 + 32;       }
        float v = NEG;
        if ((unsigned)gx < WW && (unsigned)gy < HH) {
            const int gi = gy * WW + gx;
            if (MODE == 0)      v = __ldcg(&m[gi]);
            else if (MODE == 1) v = __ldg(&xg[base + gi]) - hh;
            else if (MODE == 2) v = __ldg(&msk[base + gi]) - 1e-5f;
            else {
                float av = __ldg(&g_m[base + gi]);
                float bv = __ldg(&g_m2[base + gi]);
                float uv = __ldg(&ug[base + gi]);
                v = fminf(uv, (av > bv) ? 1.0f : 0.0f);
            }
        }
        sm[ly][lx] = v;
    }

    if (MODE == 3) {
        bool b0 = __syncthreads_or(f0);                       // also staging bar
        bool b1 = __syncthreads_or(f1);
        if (tid == 0) {
            if (b0) atomicOr(&g_rflags[0], 1);
            if (b1) atomicOr(&g_rflags[1], 1);
        }
    } else {
        __syncthreads();
    }

    float mval[4], cur[4];
#pragma unroll
    for (int k = 0; k < 4; k++) {
        mval[k] = smask[4 * ty + k][tx];
        cur[k]  = sm[4 * ty + k + 1][tx + 1];
    }

    bool any = false;
    for (int it = 0; it < 48; ++it) {
        bool ch = false;
        // down sweep (GS vertical via registers; horizontal/diag via live smem)
#pragma unroll
        for (int k = 0; k < 4; k++) {
            const int r = 4 * ty + k;                     // smem row of up-nbrs
            float up_c = (k > 0) ? cur[k - 1] : sm[r][tx + 1];
            float dn_c = (k < 3) ? cur[k + 1] : sm[r + 2][tx + 1];
            float c = fmaxf(fmaxf(sm[r][tx], up_c), sm[r][tx + 2]);
            c = fmaxf(c, fmaxf(sm[r + 1][tx], sm[r + 1][tx + 2]));
            c = fmaxf(c, fmaxf(fmaxf(sm[r + 2][tx], dn_c), sm[r + 2][tx + 2]));
            float nv = fminf(mval[k], fmaxf(cur[k], c));
            if (nv > cur[k]) { cur[k] = nv; sm[r + 1][tx + 1] = nv; ch = true; }
        }
        // up sweep (register-only vertical back-propagation)
#pragma unroll
        for (int k = 2; k >= 0; k--) {
            float nv = fminf(mval[k], fmaxf(cur[k], cur[k + 1]));
            if (nv > cur[k]) { cur[k] = nv; sm[4 * ty + k + 1][tx + 1] = nv; ch = true; }
        }
        any |= ch;
        if (!__syncthreads_or(ch)) break;
    }

    bool blkany = __syncthreads_or(any);
    if (MODE != 0 || blkany) {            // round 0: unconditional writeback
        float4 v;
        v.x = sm[sy + 1][sxs + 1];
        v.y = sm[sy + 1][sxs + 2];
        v.z = sm[sy + 1][sxs + 3];
        v.w = sm[sy + 1][sxs + 4];
        __stcg((float4*)&m[irow], v);
    }
    return blkany;
}

// ---------------------------------------------------------------------------
// Reconstruction: round 0 uses the fused staging mode; rounds >=1 generic.
// Dirty-skip + exact early exit (R4).
// ---------------------------------------------------------------------------
template<int M0>
__device__ __forceinline__ void recon(
    float* mk, const float* msk, int maxr, int flagbase,
    const float* xg, const float* hg, const float* ug, float* outg,
    unsigned nb, unsigned& target, float (*sm)[34], float (*smask)[32],
    int tid, int bid)
{
    for (int r = 0; r < maxr; ++r) {
        const int par = r & 1;
        for (int t = bid; t < NTILES; t += (int)nb) {
            bool need = true;
            if (r > 0) {
                bool mine = false;
                if (tid < 9) {
                    int dy = tid / 3 - 1, dx = tid % 3 - 1;
                    int tyy = (t >> 4) & 15, txx = t & 15;
                    int ny = tyy + dy, nx = txx + dx;
                    if ((unsigned)ny < 16u && (unsigned)nx < 16u)
                        mine = (*(volatile unsigned char*)&g_dirty[par ^ 1][t + dy * 16 + dx]) != 0;
                }
                need = __syncthreads_or(mine);
            }
            bool ch = false;
            if (need) {
                int img = t >> 8, local = t & 255;
                int xx = (local & 15) << 5, yy = ((local >> 4) & 15) << 5;
                ch = (r == 0)
                   ? process_tile<M0>(mk, msk, xg, hg, ug, outg, img, xx, yy, sm, smask, tid)
                   : process_tile<0>(mk, msk, xg, hg, ug, outg, img, xx, yy, sm, smask, tid);
            }
            if (tid == 0) {
                *(volatile unsigned char*)&g_dirty[par][t] = ch ? 1 : 0;
                if (ch) *(volatile int*)&g_chflag[flagbase + r] = 1;
            }
            __syncthreads();
        }
        gbar(nb, target);
        if (*(volatile int*)&g_chflag[flagbase + r] == 0) break;  // uniform
    }
}

// ---------------------------------------------------------------------------
// The whole pipeline in one persistent kernel.
// ---------------------------------------------------------------------------
__global__ void __launch_bounds__(256, 6) persistent_kernel(
    const float* __restrict__ x, const float* __restrict__ h,
    const float* __restrict__ u, float* __restrict__ out, int nbi)
{
    __shared__ float sm[34][34];
    __shared__ float smask[32][32];
    __shared__ float red[8];
    const unsigned nb = (unsigned)nbi;
    const int tid = threadIdx.x;
    const int bid = blockIdx.x;
    unsigned target = *((volatile unsigned*)&g_release) + 1;

    // ---- P0: reset flags/counters (marker init fused into round 0) -------
    if (bid == 0) {
        if (tid < NFLAGS) __stcg(&g_chflag[tid], 0);
        if (tid < 2)      __stcg(&g_rflags[tid], 0);
        if (tid < BB)     __stcg(&g_cc[tid], 0.0f);
    }
    gbar(nb, target);

    // ---- Rec1: xh = rec(x - h, x)  (marker computed in round 0) ----------
    recon<1>(g_m, x, MAXR1, 0, x, h, u, out, nb, target, sm, smask, tid, bid);

    // ---- Rec2: rec(xh - eps, xh)  (marker + out=xh fused into round 0) ---
    recon<2>(g_m2, g_m, MAXR2, MAXR1, x, h, u, out, nb, target, sm, smask, tid, bid);

    // ---- Rec3: R = rec(min(u,Rmax), Rmax) (Rmax/M/flags fused, r0) -------
    recon<3>(g_m3, g_rmx, MAXR3, MAXR1 + MAXR2, x, h, u, out, nb, target, sm, smask, tid, bid);

    // ---- P3: CC[img] = sum(u == R) ---------------------------------------
    {
        const int ty = tid >> 5, tx = tid & 31;
        for (int t = bid; t < NTILES; t += nbi) {
            int img = t >> 8, local = t & 255;
            int x0 = (local & 15) << 5, y0 = ((local >> 4) & 15) << 5;
            const float* uu = u + (size_t)img * IMG;
            const float* m3 = g_m3 + (size_t)img * IMG;
            float s = 0.0f;
#pragma unroll
            for (int k = 0; k < 4; k++) {
                int idx = (y0 + ty + 8 * k) * WW + x0 + tx;
                s += (__ldg(&uu[idx]) == __ldg(&m3[idx])) ? 1.0f : 0.0f;
            }
#pragma unroll
            for (int off = 16; off; off >>= 1)
                s += __shfl_down_sync(0xffffffffu, s, off);
            if ((tid & 31) == 0) red[tid >> 5] = s;
            __syncthreads();
            if (tid == 0) {
                float tot = 0.0f;
#pragma unroll
                for (int w = 0; w < 8; w++) tot += red[w];
                atomicAdd(&g_cc[img], tot);
            }
            __syncthreads();
        }
    }
    gbar(nb, target);

    // ---- P4: CC_ ---------------------------------------------------------
    if (bid == 0 && tid < BB) {
        float maxR = __ldcg(&g_rflags[1]) ? 1.0f : 0.0f;
        float minR = __ldcg(&g_rflags[0]) ? 0.0f : 1.0f;
        float diff = maxR - minR;
        float cc = *(volatile float*)&g_cc[tid];
        out[tid] = fminf(cc, 100.0f * diff * cc);
    }
}

// ---------------------------------------------------------------------------
extern "C" void kernel_launch(void* const* d_in, const int* in_sizes, int n_in,
                              void* d_out, int out_size)
{
    // Identify inputs by size (x and u are 4194304, h is 16; x precedes u)
    const float *x = nullptr, *h = nullptr, *u = nullptr;
    for (int i = 0; i < n_in; i++) {
        if (in_sizes[i] == BB) h = (const float*)d_in[i];
        else if (!x)           x = (const float*)d_in[i];
        else                   u = (const float*)d_in[i];
    }
    float* out = (float*)d_out;

    int dev = 0, sms = 0, occ = 0;
    cudaGetDevice(&dev);
    cudaDeviceGetAttribute(&sms, cudaDevAttrMultiProcessorCount, dev);
    cudaOccupancyMaxActiveBlocksPerMultiprocessor(&occ, persistent_kernel, 256, 0);
    int nb = sms * occ;
    if (nb <= 0) nb = 256;       // conservative fallback, guaranteed resident
    if (nb > 2048) nb = 2048;

    persistent_kernel<<<nb, 256>>>(x, h, u, out, nb);
}